// round 4
// baseline (speedup 1.0000x reference)
#include <cuda_runtime.h>
#include <math.h>

#define BB 4
#define CC 64
#define HH 128
#define WW 128
#define DD 256
#define NN 100
#define MAXDET 10
#define HWP (HH*WW)
#define SEG_OFF   0
#define MASK_OFF  (HWP*BB)
#define KEPT_OFF  (MASK_OFF + HWP*BB)
#define VALID_OFF (KEPT_OFF + BB*MAXDET*5)

#define TP 16                    // pixels per tile
#define RW 18                    // padded row width (72B, 8B aligned, odd word-ish stride)
#define CHUNKS 19                // ceil(17*17 / 16)

// ---------------- device scratch ----------------
__device__ int   g_ibox[BB][MAXDET][4];
__device__ int   g_valid[BB][MAXDET];
__device__ float g_seg0;

typedef unsigned long long ull;

// ---------------- packed f32x2 helpers (sm_103a) ----------------
__device__ __forceinline__ ull fma2(ull a, ull b, ull c) {
    ull d;
    asm("fma.rn.f32x2 %0, %1, %2, %3;" : "=l"(d) : "l"(a), "l"(b), "l"(c));
    return d;
}
__device__ __forceinline__ ull pack2(float x) {
    unsigned u = __float_as_uint(x);
    ull r;
    asm("mov.b64 %0, {%1, %2};" : "=l"(r) : "r"(u), "r"(u));
    return r;
}
__device__ __forceinline__ ull packf(float lo, float hi) {
    ull r;
    asm("mov.b64 %0, {%1, %2};" : "=l"(r) : "r"(__float_as_uint(lo)), "r"(__float_as_uint(hi)));
    return r;
}
__device__ __forceinline__ void unpack2(ull v, float& lo, float& hi) {
    unsigned a, b;
    asm("mov.b64 {%0, %1}, %2;" : "=r"(a), "=r"(b) : "l"(v));
    lo = __uint_as_float(a);
    hi = __uint_as_float(b);
}

// ---------------- Kernel 1: NMS (blocks 0-3) + seg0 (block 4) ----------
__global__ void __launch_bounds__(256) front_kernel(
        const float* __restrict__ rb,
        const float* __restrict__ b1v, const float* __restrict__ W2,
        const float* __restrict__ b2v, const float* __restrict__ W3,
        const float* __restrict__ b3v,
        float* __restrict__ out) {
    const int t = threadIdx.x;   // 256

    __shared__ float bx[NN*5];
    __shared__ float area[NN];
    __shared__ float iou[NN*NN];
    __shared__ int   s_any;
    __shared__ int   idxs[MAXDET];
    __shared__ int   hasA[MAXDET];
    __shared__ float h1c[DD];
    __shared__ float red[256];

    if (blockIdx.x == BB) {
        // ---- seg0: MLP applied to the all-zero word (8 accumulators, deep MLP)
        h1c[t] = fmaxf(b1v[t], 0.f);
        __syncthreads();
        float acc[8];
        #pragma unroll
        for (int j = 0; j < 8; j++) acc[j] = 0.f;
        #pragma unroll 4
        for (int d0 = 0; d0 < DD; d0 += 8) {
            #pragma unroll
            for (int j = 0; j < 8; j++)
                acc[j] += h1c[d0 + j] * W2[(d0 + j)*DD + t];
        }
        float a = b2v[t];
        #pragma unroll
        for (int j = 0; j < 8; j++) a += acc[j];
        red[t] = fmaxf(a, 0.f) * W3[t];
        __syncthreads();
        for (int off = 128; off; off >>= 1) {
            if (t < off) red[t] += red[t + off];
            __syncthreads();
        }
        if (t == 0) g_seg0 = red[0] + b3v[0];
        return;
    }

    const int b = blockIdx.x;
    for (int i = t; i < NN*5; i += 256) bx[i] = rb[b*NN*5 + i];
    if (t == 0) s_any = 0;
    __syncthreads();

    if (t < NN) {
        float a = fmaxf(bx[t*5+2]-bx[t*5+0], 0.f) * fmaxf(bx[t*5+3]-bx[t*5+1], 0.f);
        area[t] = a;
        if (bx[t*5+4] > 0.2f) atomicOr(&s_any, 1);
    }
    __syncthreads();

    for (int k = t; k < NN*NN; k += 256) {
        int i = k / NN, j = k - i*NN;
        float lx = fmaxf(bx[i*5+0], bx[j*5+0]);
        float ly = fmaxf(bx[i*5+1], bx[j*5+1]);
        float rx = fminf(bx[i*5+2], bx[j*5+2]);
        float ry = fminf(bx[i*5+3], bx[j*5+3]);
        float iw = fmaxf(rx - lx, 0.f);
        float ih = fmaxf(ry - ly, 0.f);
        float inter = iw * ih;
        iou[k] = inter / (area[i] + area[j] - inter + 1e-9f);
    }
    __syncthreads();

    // ---- warp-0 greedy NMS: candidate flags in registers, shuffle argmax
    if (t < 32) {
        const int l = t;
        const int anyv = s_any;
        float cf[4];
        int   act[4];
        #pragma unroll
        for (int m = 0; m < 4; m++) {
            int c = l + 32*m;
            bool ok = c < NN;
            cf[m]  = ok ? bx[c*5+4] : -INFINITY;
            act[m] = ok ? (anyv ? (cf[m] > 0.2f ? 1 : 0) : 1) : 0;
        }
        for (int it = 0; it < MAXDET; it++) {
            float bv = -INFINITY;
            int   bi = l;            // smallest owned idx (gives global tie -> 0)
            #pragma unroll
            for (int m = 0; m < 4; m++) {
                int c = l + 32*m;
                if (act[m] && cf[m] > bv) { bv = cf[m]; bi = c; }
            }
            #pragma unroll
            for (int off = 16; off; off >>= 1) {
                float v2 = __shfl_xor_sync(0xffffffffu, bv, off);
                int   i2 = __shfl_xor_sync(0xffffffffu, bi, off);
                if (v2 > bv || (v2 == bv && i2 < bi)) { bv = v2; bi = i2; }
            }
            bool has = bv > -INFINITY;
            if (l == 0) { idxs[it] = bi; hasA[it] = has ? 1 : 0; }
            if (has) {
                #pragma unroll
                for (int m = 0; m < 4; m++) {
                    int c = l + 32*m;
                    if (act[m] && (c == bi || iou[bi*NN + c] > 0.4f)) act[m] = 0;
                }
            }
        }
    }
    __syncthreads();

    if (t < MAXDET*5) {
        int det = t / 5, k = t - det*5;
        out[KEPT_OFF + b*MAXDET*5 + t] = bx[idxs[det]*5 + k];
    }
    if (t < MAXDET) {
        int kr = idxs[t];
        float x1f = bx[kr*5+0], y1f = bx[kr*5+1];
        float x2f = bx[kr*5+2], y2f = bx[kr*5+3];
        int v = hasA[t] && (x2f - x1f >= 1.f) && (y2f - y1f >= 1.f)
                        && (s_any ? 1 : (t < 5));
        out[VALID_OFF + b*MAXDET + t] = v ? 1.f : 0.f;
        g_valid[b][t] = v;
        int x1 = (int)floorf(x1f + 0.5f); x1 = min(max(x1, 0), WW);
        int y1 = (int)floorf(y1f + 0.5f); y1 = min(max(y1, 0), HH);
        int x2 = (int)floorf(x2f + 0.5f); x2 = min(max(x2, 0), WW);
        int y2 = (int)floorf(y2f + 0.5f); y2 = min(max(y2, 0), HH);
        g_ibox[b][t][0] = x1; g_ibox[b][t][1] = y1;
        g_ibox[b][t][2] = x2; g_ibox[b][t][3] = y2;
    }
}

// ---------------- Kernel 2: mask + default seg (per-pixel over 4 batches) --
__global__ void mask_kernel(float* __restrict__ out) {
    int p = blockIdx.x * blockDim.x + threadIdx.x;   // 0 .. HWP-1
    if (p >= HWP) return;
    int h = p >> 7;
    int w = p & (WW - 1);
    float s0 = g_seg0;
    *(float4*)&out[SEG_OFF + p*BB] = make_float4(s0, s0, s0, s0);
    #pragma unroll
    for (int b = 0; b < BB; b++) {
        bool inside = false;
        #pragma unroll
        for (int k = 0; k < MAXDET; k++) {
            if (g_valid[b][k]) {
                inside |= (w >= g_ibox[b][k][0] && w < g_ibox[b][k][2] &&
                           h >= g_ibox[b][k][1] && h < g_ibox[b][k][3]);
            }
        }
        out[MASK_OFF + b*HWP + p] = inside ? 0.f : 1.f;
    }
}

// ---------------- MLP layer: thread = 4 consecutive feats x 8 px ----------
template<int K, bool RELU, bool FINAL>
__device__ __forceinline__ void layerW(
        const float* __restrict__ Wm, const float* __restrict__ bias,
        const float* __restrict__ W3,
        const float (*in)[RW], float (*outp)[RW],
        float* partial, int f0, int pb) {
    ull acc[4][4];
    #pragma unroll
    for (int j = 0; j < 4; j++) {
        ull bj = pack2(bias[f0 + j]);
        #pragma unroll
        for (int pp = 0; pp < 4; pp++) acc[j][pp] = bj;
    }
    #pragma unroll 4
    for (int k = 0; k < K; k++) {
        float4 w4 = *(const float4*)&Wm[k*DD + f0];
        ull w0 = pack2(w4.x), w1 = pack2(w4.y), w2 = pack2(w4.z), w3 = pack2(w4.w);
        ull a0 = *(const ull*)&in[k][pb + 0];
        ull a1 = *(const ull*)&in[k][pb + 2];
        ull a2 = *(const ull*)&in[k][pb + 4];
        ull a3 = *(const ull*)&in[k][pb + 6];
        acc[0][0] = fma2(w0, a0, acc[0][0]);
        acc[0][1] = fma2(w0, a1, acc[0][1]);
        acc[0][2] = fma2(w0, a2, acc[0][2]);
        acc[0][3] = fma2(w0, a3, acc[0][3]);
        acc[1][0] = fma2(w1, a0, acc[1][0]);
        acc[1][1] = fma2(w1, a1, acc[1][1]);
        acc[1][2] = fma2(w1, a2, acc[1][2]);
        acc[1][3] = fma2(w1, a3, acc[1][3]);
        acc[2][0] = fma2(w2, a0, acc[2][0]);
        acc[2][1] = fma2(w2, a1, acc[2][1]);
        acc[2][2] = fma2(w2, a2, acc[2][2]);
        acc[2][3] = fma2(w2, a3, acc[2][3]);
        acc[3][0] = fma2(w3, a0, acc[3][0]);
        acc[3][1] = fma2(w3, a1, acc[3][1]);
        acc[3][2] = fma2(w3, a2, acc[3][2]);
        acc[3][3] = fma2(w3, a3, acc[3][3]);
    }
    #pragma unroll
    for (int j = 0; j < 4; j++) {
        float v[8];
        #pragma unroll
        for (int pp = 0; pp < 4; pp++) unpack2(acc[j][pp], v[2*pp], v[2*pp+1]);
        if (RELU) {
            #pragma unroll
            for (int i = 0; i < 8; i++) v[i] = fmaxf(v[i], 0.f);
        }
        if (FINAL) {
            float w3v = W3[f0 + j];
            #pragma unroll
            for (int i = 0; i < 8; i++) partial[i] += v[i] * w3v;
        } else {
            #pragma unroll
            for (int pp = 0; pp < 4; pp++)
                *(ull*)&outp[f0 + j][pb + 2*pp] = packf(v[2*pp], v[2*pp+1]);
        }
    }
}

// ---------------- Kernel 3: per-box-chunk MLP ----------------
__global__ void __launch_bounds__(128) mlp_kernel(
        const float* __restrict__ x,
        const float* __restrict__ W_sem, const float* __restrict__ b_sem,
        const float* __restrict__ W1, const float* __restrict__ b1,
        const float* __restrict__ W2, const float* __restrict__ b2,
        const float* __restrict__ W3, const float* __restrict__ b3,
        float* __restrict__ out) {
    __shared__ __align__(16) float sx[CC][RW];
    __shared__ __align__(16) float sA[DD][RW];
    __shared__ __align__(16) float sB[DD][RW];
    __shared__ float stage[128][8];
    __shared__ int spix[TP];

    const int b   = blockIdx.z;
    const int det = blockIdx.y;
    if (!g_valid[b][det]) return;
    const int x1 = g_ibox[b][det][0], y1 = g_ibox[b][det][1];
    const int x2 = g_ibox[b][det][2], y2 = g_ibox[b][det][3];
    const int wdt = x2 - x1;
    const int area = wdt * (y2 - y1);
    const int base = blockIdx.x * TP;
    if (base >= area) return;
    const int rem = min(area - base, TP);

    const int tid = threadIdx.x;      // 128
    if (tid < TP) {
        int idx = base + (tid < rem ? tid : 0);
        int py = y1 + idx / wdt;
        int px = x1 + idx % wdt;
        spix[tid] = py * WW + px;
    }
    __syncthreads();

    // gather x transposed: sx[c][p]
    for (int i = tid; i < CC*TP; i += 128) {
        int c = i >> 4, p = i & (TP - 1);
        sx[c][p] = x[((b << 6) + c) * HWP + spix[p]];
    }
    __syncthreads();

    const int warp = tid >> 5;        // 0..3
    const int l    = tid & 31;
    const int f0   = (warp & 1) * 128 + 4 * l;   // 4 consecutive features
    const int pb   = (warp >> 1) * 8;            // 8-pixel half

    float partial[8];
    #pragma unroll
    for (int i = 0; i < 8; i++) partial[i] = 0.f;

    layerW<CC,  false, false>(W_sem, b_sem, nullptr, sx, sA, nullptr, f0, pb);
    __syncthreads();
    layerW<DD,  true,  false>(W1,    b1,    nullptr, sA, sB, nullptr, f0, pb);
    __syncthreads();
    layerW<DD,  true,  true >(W2,    b2,    W3,      sB, nullptr, partial, f0, pb);

    // stage partials and reduce deterministically
    #pragma unroll
    for (int i = 0; i < 8; i++) stage[tid][i] = partial[i];
    __syncthreads();

    if (tid < TP) {
        int p = tid;
        int grp = p >> 3;       // pixel half -> thread group [grp*64, grp*64+64)
        int col = p & 7;
        float s = 0.f;
        #pragma unroll 8
        for (int q = 0; q < 64; q++) s += stage[grp*64 + q][col];
        if (p < rem) out[SEG_OFF + spix[p]*BB + b] = s + b3[0];
    }
}

// ---------------- launch ----------------
extern "C" void kernel_launch(void* const* d_in, const int* in_sizes, int n_in,
                              void* d_out, int out_size) {
    (void)in_sizes; (void)n_in; (void)out_size;
    const float* x     = (const float*)d_in[0];
    const float* rb    = (const float*)d_in[1];
    const float* W_sem = (const float*)d_in[2];
    const float* b_sem = (const float*)d_in[3];
    const float* W1    = (const float*)d_in[4];
    const float* b1    = (const float*)d_in[5];
    const float* W2    = (const float*)d_in[6];
    const float* b2    = (const float*)d_in[7];
    const float* W3    = (const float*)d_in[8];
    const float* b3    = (const float*)d_in[9];
    float* out = (float*)d_out;

    front_kernel<<<BB + 1, 256>>>(rb, b1, W2, b2, W3, b3, out);
    mask_kernel<<<HWP/256, 256>>>(out);
    mlp_kernel<<<dim3(CHUNKS, MAXDET, BB), 128>>>(x, W_sem, b_sem, W1, b1, W2, b2, W3, b3, out);
}

// round 5
// speedup vs baseline: 1.3417x; 1.3417x over previous
#include <cuda_runtime.h>
#include <math.h>

#define BB 4
#define CC 64
#define HH 128
#define WW 128
#define DD 256
#define NN 100
#define MAXDET 10
#define HWP (HH*WW)
#define SEG_OFF   0
#define MASK_OFF  (HWP*BB)
#define KEPT_OFF  (MASK_OFF + HWP*BB)
#define VALID_OFF (KEPT_OFF + BB*MAXDET*5)

#define TP 16                    // pixels per tile
#define MAXTILES 723             // ceil(4*10*17*17 / 16)
#define NPART 16                 // seg0 partial blocks

// ---------------- device scratch ----------------
__device__ int   g_ibox[BB][MAXDET][4];
__device__ int   g_valid[BB][MAXDET];
__device__ float g_seg0;
__device__ float g_part[NPART][DD];
__device__ int   g_count;
__device__ int   g_list[BB*HWP];

typedef unsigned long long ull;

// ---------------- packed f32x2 helpers (sm_103a) ----------------
__device__ __forceinline__ ull fma2(ull a, ull b, ull c) {
    ull d;
    asm("fma.rn.f32x2 %0, %1, %2, %3;" : "=l"(d) : "l"(a), "l"(b), "l"(c));
    return d;
}
__device__ __forceinline__ ull pack2(float x) {
    unsigned u = __float_as_uint(x);
    ull r;
    asm("mov.b64 %0, {%1, %2};" : "=l"(r) : "r"(u), "r"(u));
    return r;
}
__device__ __forceinline__ void unpack2(ull v, float& lo, float& hi) {
    unsigned a, b;
    asm("mov.b64 {%0, %1}, %2;" : "=r"(a), "=r"(b) : "l"(v));
    lo = __uint_as_float(a);
    hi = __uint_as_float(b);
}

// ---------------- Kernel 1: NMS (blocks 0-3) + seg0 partials (4..19) ------
__global__ void __launch_bounds__(256) front_kernel(
        const float* __restrict__ rb,
        const float* __restrict__ b1v, const float* __restrict__ W2,
        float* __restrict__ out) {
    const int t = threadIdx.x;   // 256

    if (blockIdx.x >= BB) {
        // seg0 partial: rows [blk*16, blk*16+16) of h1 @ W2
        const int blk = blockIdx.x - BB;
        const int d0 = blk * 16;
        float h1[16];
        #pragma unroll
        for (int j = 0; j < 16; j++) h1[j] = fmaxf(__ldg(&b1v[d0 + j]), 0.f);
        float acc = 0.f;
        #pragma unroll
        for (int j = 0; j < 16; j++) acc += h1[j] * __ldg(&W2[(d0 + j)*DD + t]);
        g_part[blk][t] = acc;
        return;
    }

    const int b = blockIdx.x;
    __shared__ float bx[NN*5];
    __shared__ float area[NN];
    __shared__ float iou[NN*NN];
    __shared__ int   s_any;
    __shared__ int   idxs[MAXDET];
    __shared__ int   hasA[MAXDET];

    for (int i = t; i < NN*5; i += 256) bx[i] = rb[b*NN*5 + i];
    if (t == 0) s_any = 0;
    __syncthreads();

    if (t < NN) {
        float a = fmaxf(bx[t*5+2]-bx[t*5+0], 0.f) * fmaxf(bx[t*5+3]-bx[t*5+1], 0.f);
        area[t] = a;
        if (bx[t*5+4] > 0.2f) atomicOr(&s_any, 1);
    }
    __syncthreads();

    for (int k = t; k < NN*NN; k += 256) {
        int i = k / NN, j = k - i*NN;
        float lx = fmaxf(bx[i*5+0], bx[j*5+0]);
        float ly = fmaxf(bx[i*5+1], bx[j*5+1]);
        float rx = fminf(bx[i*5+2], bx[j*5+2]);
        float ry = fminf(bx[i*5+3], bx[j*5+3]);
        float iw = fmaxf(rx - lx, 0.f);
        float ih = fmaxf(ry - ly, 0.f);
        float inter = iw * ih;
        iou[k] = inter / (area[i] + area[j] - inter + 1e-9f);
    }
    __syncthreads();

    // ---- warp-0 greedy NMS
    if (t < 32) {
        const int l = t;
        const int anyv = s_any;
        float cf[4];
        int   act[4];
        #pragma unroll
        for (int m = 0; m < 4; m++) {
            int c = l + 32*m;
            bool ok = c < NN;
            cf[m]  = ok ? bx[c*5+4] : -INFINITY;
            act[m] = ok ? (anyv ? (cf[m] > 0.2f ? 1 : 0) : 1) : 0;
        }
        for (int it = 0; it < MAXDET; it++) {
            float bv = -INFINITY;
            int   bi = l;
            #pragma unroll
            for (int m = 0; m < 4; m++) {
                int c = l + 32*m;
                if (act[m] && cf[m] > bv) { bv = cf[m]; bi = c; }
            }
            #pragma unroll
            for (int off = 16; off; off >>= 1) {
                float v2 = __shfl_xor_sync(0xffffffffu, bv, off);
                int   i2 = __shfl_xor_sync(0xffffffffu, bi, off);
                if (v2 > bv || (v2 == bv && i2 < bi)) { bv = v2; bi = i2; }
            }
            bool has = bv > -INFINITY;
            if (l == 0) { idxs[it] = bi; hasA[it] = has ? 1 : 0; }
            if (has) {
                #pragma unroll
                for (int m = 0; m < 4; m++) {
                    int c = l + 32*m;
                    if (act[m] && (c == bi || iou[bi*NN + c] > 0.4f)) act[m] = 0;
                }
            }
        }
    }
    __syncthreads();

    if (t < MAXDET*5) {
        int det = t / 5, k = t - det*5;
        out[KEPT_OFF + b*MAXDET*5 + t] = bx[idxs[det]*5 + k];
    }
    if (t < MAXDET) {
        int kr = idxs[t];
        float x1f = bx[kr*5+0], y1f = bx[kr*5+1];
        float x2f = bx[kr*5+2], y2f = bx[kr*5+3];
        int v = hasA[t] && (x2f - x1f >= 1.f) && (y2f - y1f >= 1.f)
                        && (s_any ? 1 : (t < 5));
        out[VALID_OFF + b*MAXDET + t] = v ? 1.f : 0.f;
        g_valid[b][t] = v;
        int x1 = (int)floorf(x1f + 0.5f); x1 = min(max(x1, 0), WW);
        int y1 = (int)floorf(y1f + 0.5f); y1 = min(max(y1, 0), HH);
        int x2 = (int)floorf(x2f + 0.5f); x2 = min(max(x2, 0), WW);
        int y2 = (int)floorf(y2f + 0.5f); y2 = min(max(y2, 0), HH);
        g_ibox[b][t][0] = x1; g_ibox[b][t][1] = y1;
        g_ibox[b][t][2] = x2; g_ibox[b][t][3] = y2;
    }
}

// ---------------- Kernel 2: combine seg0 partials ----------------
__global__ void __launch_bounds__(256) combine_kernel(
        const float* __restrict__ b2v, const float* __restrict__ W3,
        const float* __restrict__ b3v) {
    __shared__ float red[256];
    const int t = threadIdx.x;
    float acc = b2v[t];
    #pragma unroll
    for (int blk = 0; blk < NPART; blk++) acc += g_part[blk][t];
    red[t] = fmaxf(acc, 0.f) * W3[t];
    __syncthreads();
    for (int off = 128; off; off >>= 1) {
        if (t < off) red[t] += red[t + off];
        __syncthreads();
    }
    if (t == 0) { g_seg0 = red[0] + b3v[0]; g_count = 0; }
}

// ---------------- Kernel 3: mask + default seg + compact ----------------
__global__ void mask_kernel(float* __restrict__ out) {
    int p = blockIdx.x * blockDim.x + threadIdx.x;   // 0 .. HWP-1
    if (p >= HWP) return;
    int h = p >> 7;
    int w = p & (WW - 1);
    float s0 = g_seg0;
    *(float4*)&out[SEG_OFF + p*BB] = make_float4(s0, s0, s0, s0);
    #pragma unroll
    for (int b = 0; b < BB; b++) {
        bool inside = false;
        #pragma unroll
        for (int k = 0; k < MAXDET; k++) {
            if (g_valid[b][k]) {
                inside |= (w >= g_ibox[b][k][0] && w < g_ibox[b][k][2] &&
                           h >= g_ibox[b][k][1] && h < g_ibox[b][k][3]);
            }
        }
        out[MASK_OFF + b*HWP + p] = inside ? 0.f : 1.f;
        if (inside) {
            int pos = atomicAdd(&g_count, 1);
            g_list[pos] = (b << 14) | p;
        }
    }
}

// ---------------- MLP layer: thread = 2 consecutive feats x 8 px ----------
template<int K, bool RELU, bool FINAL>
__device__ __forceinline__ void layer2f(
        const float* __restrict__ Wm, const float* __restrict__ bias,
        const float* __restrict__ W3,
        const float (*in)[TP], float (*outp)[TP],
        float* partial, int f0, int pb) {
    ull a0[4], a1[4];
    {
        float2 bb = *(const float2*)&bias[f0];
        ull b0 = pack2(bb.x), b1 = pack2(bb.y);
        #pragma unroll
        for (int pp = 0; pp < 4; pp++) { a0[pp] = b0; a1[pp] = b1; }
    }
    #pragma unroll 8
    for (int k = 0; k < K; k++) {
        float2 w = *(const float2*)&Wm[k*DD + f0];
        ull w0 = pack2(w.x), w1 = pack2(w.y);
        ulonglong2 x01 = *(const ulonglong2*)&in[k][pb];
        ulonglong2 x23 = *(const ulonglong2*)&in[k][pb + 4];
        a0[0] = fma2(w0, x01.x, a0[0]);
        a0[1] = fma2(w0, x01.y, a0[1]);
        a0[2] = fma2(w0, x23.x, a0[2]);
        a0[3] = fma2(w0, x23.y, a0[3]);
        a1[0] = fma2(w1, x01.x, a1[0]);
        a1[1] = fma2(w1, x01.y, a1[1]);
        a1[2] = fma2(w1, x23.x, a1[2]);
        a1[3] = fma2(w1, x23.y, a1[3]);
    }
    float v0[8], v1[8];
    #pragma unroll
    for (int pp = 0; pp < 4; pp++) {
        unpack2(a0[pp], v0[2*pp], v0[2*pp+1]);
        unpack2(a1[pp], v1[2*pp], v1[2*pp+1]);
    }
    if (RELU) {
        #pragma unroll
        for (int i = 0; i < 8; i++) { v0[i] = fmaxf(v0[i], 0.f); v1[i] = fmaxf(v1[i], 0.f); }
    }
    if (FINAL) {
        float2 w3 = *(const float2*)&W3[f0];
        #pragma unroll
        for (int i = 0; i < 8; i++) partial[i] += v0[i]*w3.x + v1[i]*w3.y;
    } else {
        float4* o0 = (float4*)&outp[f0][pb];
        o0[0] = make_float4(v0[0], v0[1], v0[2], v0[3]);
        o0[1] = make_float4(v0[4], v0[5], v0[6], v0[7]);
        float4* o1 = (float4*)&outp[f0+1][pb];
        o1[0] = make_float4(v1[0], v1[1], v1[2], v1[3]);
        o1[1] = make_float4(v1[4], v1[5], v1[6], v1[7]);
    }
}

// ---------------- Kernel 4: compacted-tile MLP ----------------
__global__ void __launch_bounds__(256) mlp_kernel(
        const float* __restrict__ x,
        const float* __restrict__ W_sem, const float* __restrict__ b_sem,
        const float* __restrict__ W1, const float* __restrict__ b1,
        const float* __restrict__ W2, const float* __restrict__ b2,
        const float* __restrict__ W3, const float* __restrict__ b3,
        float* __restrict__ out) {
    __shared__ __align__(16) float sx[CC][TP];
    __shared__ __align__(16) float sA[DD][TP];
    __shared__ __align__(16) float sB[DD][TP];
    __shared__ float stage[256][8];
    __shared__ int spix[TP];

    const int count  = g_count;
    const int ntiles = (count + TP - 1) / TP;
    const int tile = blockIdx.x;
    if (tile >= ntiles) return;
    const int base = tile * TP;
    const int rem  = min(count - base, TP);

    const int tid = threadIdx.x;      // 256
    if (tid < TP) {
        spix[tid] = g_list[tid < rem ? base + tid : base];
    }
    __syncthreads();

    // gather x transposed: sx[c][p]
    for (int i = tid; i < CC*TP; i += 256) {
        int c = i >> 4, p = i & (TP - 1);
        int gid = spix[p];
        int b = gid >> 14, pp = gid & (HWP - 1);
        sx[c][p] = x[((b << 6) + c) * HWP + pp];
    }
    __syncthreads();

    const int warp = tid >> 5;                 // 0..7
    const int l    = tid & 31;
    const int f0   = (warp & 3) * 64 + 2 * l;  // 2 consecutive features
    const int pb   = (warp >> 2) * 8;          // pixel half

    float partial[8];
    #pragma unroll
    for (int i = 0; i < 8; i++) partial[i] = 0.f;

    layer2f<CC, false, false>(W_sem, b_sem, nullptr, sx, sA, nullptr, f0, pb);
    __syncthreads();
    layer2f<DD, true,  false>(W1,    b1,    nullptr, sA, sB, nullptr, f0, pb);
    __syncthreads();
    layer2f<DD, true,  true >(W2,    b2,    W3,      sB, nullptr, partial, f0, pb);

    // deterministic staged reduction over the 128 threads of each pixel half
    #pragma unroll
    for (int i = 0; i < 8; i++) stage[tid][i] = partial[i];
    __syncthreads();
    #pragma unroll
    for (int off = 64; off >= 1; off >>= 1) {
        if ((tid & 127) < off) {
            #pragma unroll
            for (int i = 0; i < 8; i++) stage[tid][i] += stage[tid + off][i];
        }
        __syncthreads();
    }
    if (tid < rem) {
        int half = tid >> 3, col = tid & 7;
        float s = stage[half * 128][col];
        int gid = spix[tid];
        int b = gid >> 14, pp = gid & (HWP - 1);
        out[SEG_OFF + pp*BB + b] = s + b3[0];
    }
}

// ---------------- launch ----------------
extern "C" void kernel_launch(void* const* d_in, const int* in_sizes, int n_in,
                              void* d_out, int out_size) {
    (void)in_sizes; (void)n_in; (void)out_size;
    const float* x     = (const float*)d_in[0];
    const float* rb    = (const float*)d_in[1];
    const float* W_sem = (const float*)d_in[2];
    const float* b_sem = (const float*)d_in[3];
    const float* W1    = (const float*)d_in[4];
    const float* b1    = (const float*)d_in[5];
    const float* W2    = (const float*)d_in[6];
    const float* b2    = (const float*)d_in[7];
    const float* W3    = (const float*)d_in[8];
    const float* b3    = (const float*)d_in[9];
    float* out = (float*)d_out;

    front_kernel<<<BB + NPART, 256>>>(rb, b1, W2, out);
    combine_kernel<<<1, 256>>>(b2, W3, b3);
    mask_kernel<<<HWP/256, 256>>>(out);
    mlp_kernel<<<MAXTILES, 256>>>(x, W_sem, b_sem, W1, b1, W2, b2, W3, b3, out);
}